// round 16
// baseline (speedup 1.0000x reference)
#include <cuda_runtime.h>
#include <cuda_fp16.h>
#include <stdint.h>

// ============================================================
// Conv 3x3 pad=1 as fp16 implicit GEMM on HMMA, A-union tiling.
// R16: units = full taps (9 units x 8 k-steps, 128 channels), B staged
// as full-K rows (ROWB_B=272), double-buffered. Halves barrier count
// (18 -> 9) and doubles the inter-barrier window so warp phases drift
// and LDS overlaps HMMA. A-union persistent (2 chunks). 1 CTA/SM.
// ============================================================

#define NPLANE 1156

__device__ __align__(256) __half g_xh[32 * NPLANE * 128];
__device__ __align__(256) __half g_wh[9 * 128 * 128];

__device__ __forceinline__ uint32_t smem_u32(const void* p) {
    uint32_t a;
    asm("{ .reg .u64 t; cvta.to.shared.u64 t, %1; cvt.u32.u64 %0, t; }" : "=r"(a) : "l"(p));
    return a;
}

#define CP_ASYNC16(dst, src, sz) \
    asm volatile("cp.async.cg.shared.global [%0], [%1], 16, %2;" :: "r"(dst), "l"(src), "r"(sz) : "memory")

__device__ __forceinline__ void ldm_x4(uint32_t* r, uint32_t addr) {
    asm volatile("ldmatrix.sync.aligned.m8n8.x4.shared.b16 {%0,%1,%2,%3}, [%4];"
                 : "=r"(r[0]), "=r"(r[1]), "=r"(r[2]), "=r"(r[3]) : "r"(addr));
}

__device__ __forceinline__ void mma_f16(float* c, const uint32_t* a, const uint32_t* b) {
    asm volatile(
        "mma.sync.aligned.m16n8k16.row.col.f32.f16.f16.f32 "
        "{%0,%1,%2,%3}, {%4,%5,%6,%7}, {%8,%9}, {%0,%1,%2,%3};"
        : "+f"(c[0]), "+f"(c[1]), "+f"(c[2]), "+f"(c[3])
        : "r"(a[0]), "r"(a[1]), "r"(a[2]), "r"(a[3]), "r"(b[0]), "r"(b[1]));
}

// ---------------- merged prep kernel ----------------

__global__ void prep_all(const float* __restrict__ x, const float* __restrict__ w) {
    const int bx = blockIdx.x, n = blockIdx.y, t = threadIdx.x;

    if (bx == 37) {
        #pragma unroll
        for (int r = 0; r < 2; ++r) {
            int id = n * 256 + t + r * 8192;
            int f = id >> 7, c = id & 127;
            const float* wp = w + (size_t)(f * 128 + c) * 9;
            #pragma unroll
            for (int q = 0; q < 9; ++q)
                g_wh[(q * 128 + f) * 128 + c] = __float2half(wp[q]);
        }
        return;
    }

    __shared__ float s[128][33];
    const int p0 = bx * 32;
    const int lane = t & 31, wrp = t >> 5;

    {
        int p = p0 + lane;
        int ph = p / 34, pw = p - ph * 34;
        int h = ph - 1, ww = pw - 1;
        bool ok = (p < NPLANE) && ((unsigned)h < 32u) && ((unsigned)ww < 32u);
        const float* xb = x + ((size_t)n * 128) * 1024 + h * 32 + ww;
        #pragma unroll
        for (int k = 0; k < 16; ++k) {
            int c = wrp * 16 + k;
            s[c][lane] = ok ? xb[(size_t)c * 1024] : 0.0f;
        }
    }
    __syncthreads();
    {
        int i = lane, cb = wrp * 16;
        int p = p0 + i;
        if (p < NPLANE) {
            __align__(16) __half hb[16];
            #pragma unroll
            for (int j = 0; j < 16; ++j) hb[j] = __float2half(s[cb + j][i]);
            size_t base = ((size_t)(n * NPLANE + p)) * 128 + cb;
            *(uint4*)(&g_xh[base])     = *(uint4*)(hb);
            *(uint4*)(&g_xh[base + 8]) = *(uint4*)(hb + 8);
        }
    }
}

// ---------------- main GEMM kernel ----------------
// 288 CTAs x 512 thr (16 warps, grid 4Mx4N, warp tile 32x32).
// SMEM: A-union 2 chunks x [204 rows][144B] @0 (persistent);
//       B ring 2 x [128 rows][272B] @58752 (full K=128 per tap).
// 9 units (taps); unit u: 8 k-steps, A chunk = ks>>2, B col ks*32.

#define ROWB 144
#define A_STAGE 29376
#define B_BASE 58752
#define ROWB_B 272
#define B_STAGE 34816
#define SMEM_DYN 128384
#define NUNITS 9
#define EPSTRIDE 18

__global__ __launch_bounds__(512, 1)
void conv_hmma(const float* __restrict__ bias, float* __restrict__ out) {
    extern __shared__ char dynsmem[];
    __shared__ float bias_s[128];

    const int tid = threadIdx.x, wid = tid >> 5, lane = tid & 31;
    const int wm = wid >> 2, wn = wid & 3;
    const int T = blockIdx.x;
    const int n = T / 9, m0 = (T % 9) * 128;

    if (tid < 128) bias_s[tid] = bias[tid];

    const uint32_t sd = smem_u32(dynsmem);

    auto load_A = [&](int chunk) {
        const uint32_t abase = sd + chunk * A_STAGE;
        const int c0 = chunk * 64;
        #pragma unroll
        for (int it = 0; it < 4; ++it) {
            int idx = it * 512 + tid;
            if (idx < 1632) {
                int row = idx >> 3, ch = idx & 7;
                int p = m0 + row;
                int sz = 16;
                if (p >= NPLANE) { p = 0; sz = 0; }
                CP_ASYNC16(abase + row * ROWB + ch * 16,
                           g_xh + ((size_t)(n * NPLANE + p)) * 128 + c0 + ch * 8, sz);
            }
        }
    };

    auto load_B = [&](int u) {      // full tap: 128 rows x 16 x 16B = 2048 pieces
        const int q = u;
        const uint32_t bbase = sd + B_BASE + (u & 1) * B_STAGE;
        #pragma unroll
        for (int it = 0; it < 4; ++it) {
            int idx = it * 512 + tid;
            int row = idx >> 4, ch = idx & 15;
            CP_ASYNC16(bbase + row * ROWB_B + ch * 16,
                       g_wh + (size_t)((q * 128 + row) * 128) + ch * 8, 16);
        }
    };

    float acc[2][4][4];
    #pragma unroll
    for (int i = 0; i < 2; ++i)
        #pragma unroll
        for (int j = 0; j < 4; ++j)
            #pragma unroll
            for (int r = 0; r < 4; ++r) acc[i][j][r] = 0.0f;

    const uint32_t a_lrow = (uint32_t)(wm * 32 + (lane & 15)) * ROWB + ((lane >> 4) << 4);
    const uint32_t b_lrow = (uint32_t)(wn * 32 + ((lane >> 4) << 3) + (lane & 7)) * ROWB_B
                            + ((lane & 8) ? 16u : 0u);

    // prologue: one group = {B0, A0, A1}
    load_B(0);
    load_A(0);
    load_A(1);
    asm volatile("cp.async.commit_group;" ::: "memory");

    for (int u = 0; u < NUNITS; ++u) {
        asm volatile("cp.async.wait_group 0;" ::: "memory");
        __syncthreads();                  // loads visible; all warps past u-1
        if (u + 1 < NUNITS) {             // prefetch next tap, overlaps compute(u)
            load_B(u + 1);
            asm volatile("cp.async.commit_group;" ::: "memory");
        }

        const int shift = (u / 3) * 34 + (u % 3);
        const uint32_t abase0 = sd + (uint32_t)shift * ROWB + a_lrow;
        const uint32_t bbase = sd + B_BASE + (u & 1) * B_STAGE + b_lrow;

        #pragma unroll
        for (int ks = 0; ks < 8; ++ks) {
            uint32_t Ah[8], Bh[8];
            const uint32_t ao = abase0 + (ks >> 2) * A_STAGE + (ks & 3) * 32;
            ldm_x4(&Ah[0], ao);
            ldm_x4(&Ah[4], ao + 16 * ROWB);
            const uint32_t bo = bbase + ks * 32;
            ldm_x4(&Bh[0], bo);
            ldm_x4(&Bh[4], bo + 16 * ROWB_B);

            #pragma unroll
            for (int i = 0; i < 2; ++i)
                #pragma unroll
                for (int j = 0; j < 4; ++j)
                    mma_f16(acc[i][j], &Ah[4 * i], &Bh[(j >> 1) * 4 + (j & 1) * 2]);
        }
    }

    __syncthreads();

    // ---------------- epilogue: 2 f-chunks of 16 via smem ----------------
    float* eps = (float*)dynsmem + wid * (32 * EPSTRIDE);
    const int g = lane >> 2, tg = lane & 3;
    const int mwbase = m0 + wm * 32;
    float* outn = out + (size_t)n * 128 * 1024;

    #pragma unroll
    for (int cj = 0; cj < 2; ++cj) {
        __syncwarp();
        #pragma unroll
        for (int i = 0; i < 2; ++i)
            #pragma unroll
            for (int jj = 0; jj < 2; ++jj) {
                int j = cj * 2 + jj;
                float* p0 = &eps[(i * 16 + g) * EPSTRIDE + jj * 8 + 2 * tg];
                float* p1 = &eps[(i * 16 + g + 8) * EPSTRIDE + jj * 8 + 2 * tg];
                *(float2*)p0 = make_float2(acc[i][j][0], acc[i][j][1]);
                *(float2*)p1 = make_float2(acc[i][j][2], acc[i][j][3]);
            }
        __syncwarp();

        #pragma unroll 1
        for (int f = 0; f < 16; ++f) {
            const int fg = wn * 32 + cj * 16 + f;
            const float bv = bias_s[fg];
            int m = mwbase + lane;
            int hh = m / 34, ww = m % 34;
            if (hh < 32 && ww < 32)
                outn[(size_t)fg * 1024 + hh * 32 + ww] = eps[lane * EPSTRIDE + f] + bv;
        }
    }
}

// ---------------- launch ----------------

extern "C" void kernel_launch(void* const* d_in, const int* in_sizes, int n_in,
                              void* d_out, int out_size) {
    const float* x = (const float*)d_in[0];
    const float* w = (const float*)d_in[1];
    const float* b = (const float*)d_in[2];
    float* out = (float*)d_out;

    cudaFuncSetAttribute(conv_hmma, cudaFuncAttributeMaxDynamicSharedMemorySize, SMEM_DYN);

    dim3 gp(38, 32);
    prep_all<<<gp, 256>>>(x, w);
    conv_hmma<<<288, 512, SMEM_DYN>>>(b, out);
}

// round 17
// speedup vs baseline: 1.0988x; 1.0988x over previous
#include <cuda_runtime.h>
#include <cuda_fp16.h>
#include <stdint.h>

// ============================================================
// Conv 3x3 pad=1 as fp16 implicit GEMM on HMMA, A-union tiling.
// R17 = R8 main loop (proven best: 34.2us, 512 thr, 32x32 warp tiles,
// 2 CTA/SM, 18 units, wait_group 0) + merged prep_all (measured
// prep+gap 4.5-4.8us vs 7.3 for split prep). No other changes.
// ============================================================

#define NPLANE 1156

__device__ __align__(256) __half g_xh[32 * NPLANE * 128];
__device__ __align__(256) __half g_wh[9 * 128 * 128];

__device__ __forceinline__ uint32_t smem_u32(const void* p) {
    uint32_t a;
    asm("{ .reg .u64 t; cvta.to.shared.u64 t, %1; cvt.u32.u64 %0, t; }" : "=r"(a) : "l"(p));
    return a;
}

#define CP_ASYNC16(dst, src, sz) \
    asm volatile("cp.async.cg.shared.global [%0], [%1], 16, %2;" :: "r"(dst), "l"(src), "r"(sz) : "memory")

__device__ __forceinline__ void ldm_x4(uint32_t* r, uint32_t addr) {
    asm volatile("ldmatrix.sync.aligned.m8n8.x4.shared.b16 {%0,%1,%2,%3}, [%4];"
                 : "=r"(r[0]), "=r"(r[1]), "=r"(r[2]), "=r"(r[3]) : "r"(addr));
}

__device__ __forceinline__ void mma_f16(float* c, const uint32_t* a, const uint32_t* b) {
    asm volatile(
        "mma.sync.aligned.m16n8k16.row.col.f32.f16.f16.f32 "
        "{%0,%1,%2,%3}, {%4,%5,%6,%7}, {%8,%9}, {%0,%1,%2,%3};"
        : "+f"(c[0]), "+f"(c[1]), "+f"(c[2]), "+f"(c[3])
        : "r"(a[0]), "r"(a[1]), "r"(a[2]), "r"(a[3]), "r"(b[0]), "r"(b[1]));
}

// ---------------- merged prep kernel ----------------

__global__ void prep_all(const float* __restrict__ x, const float* __restrict__ w) {
    const int bx = blockIdx.x, n = blockIdx.y, t = threadIdx.x;

    if (bx == 37) {
        #pragma unroll
        for (int r = 0; r < 2; ++r) {
            int id = n * 256 + t + r * 8192;
            int f = id >> 7, c = id & 127;
            const float* wp = w + (size_t)(f * 128 + c) * 9;
            #pragma unroll
            for (int q = 0; q < 9; ++q)
                g_wh[(q * 128 + f) * 128 + c] = __float2half(wp[q]);
        }
        return;
    }

    __shared__ float s[128][33];
    const int p0 = bx * 32;
    const int lane = t & 31, wrp = t >> 5;

    {
        int p = p0 + lane;
        int ph = p / 34, pw = p - ph * 34;
        int h = ph - 1, ww = pw - 1;
        bool ok = (p < NPLANE) && ((unsigned)h < 32u) && ((unsigned)ww < 32u);
        const float* xb = x + ((size_t)n * 128) * 1024 + h * 32 + ww;
        #pragma unroll
        for (int k = 0; k < 16; ++k) {
            int c = wrp * 16 + k;
            s[c][lane] = ok ? xb[(size_t)c * 1024] : 0.0f;
        }
    }
    __syncthreads();
    {
        int i = lane, cb = wrp * 16;
        int p = p0 + i;
        if (p < NPLANE) {
            __align__(16) __half hb[16];
            #pragma unroll
            for (int j = 0; j < 16; ++j) hb[j] = __float2half(s[cb + j][i]);
            size_t base = ((size_t)(n * NPLANE + p)) * 128 + cb;
            *(uint4*)(&g_xh[base])     = *(uint4*)(hb);
            *(uint4*)(&g_xh[base + 8]) = *(uint4*)(hb + 8);
        }
    }
}

// ---------------- main GEMM kernel (R8 verbatim) ----------------
// 288 CTAs x 512 thr (16 warps, grid 4Mx4N, warp tile 32x32).
// SMEM rows 144B: A-union 2 x [204][144] @0; B ring 2 x [128][144] @58752.

#define ROWB 144
#define A_STAGE 29376
#define B_BASE 58752
#define B_STAGE 18432
#define SMEM_DYN 95616
#define NUNITS 18
#define EPSTRIDE 18

__global__ __launch_bounds__(512, 2)
void conv_hmma(const float* __restrict__ bias, float* __restrict__ out) {
    extern __shared__ char dynsmem[];
    __shared__ float bias_s[128];

    const int tid = threadIdx.x, wid = tid >> 5, lane = tid & 31;
    const int wm = wid >> 2, wn = wid & 3;
    const int T = blockIdx.x;
    const int n = T / 9, m0 = (T % 9) * 128;

    if (tid < 128) bias_s[tid] = bias[tid];

    const uint32_t sd = smem_u32(dynsmem);

    auto load_A = [&](int chunk) {
        const uint32_t abase = sd + chunk * A_STAGE;
        const int c0 = chunk * 64;
        #pragma unroll
        for (int it = 0; it < 4; ++it) {
            int idx = it * 512 + tid;
            if (idx < 1632) {
                int row = idx >> 3, ch = idx & 7;
                int p = m0 + row;
                int sz = 16;
                if (p >= NPLANE) { p = 0; sz = 0; }
                CP_ASYNC16(abase + row * ROWB + ch * 16,
                           g_xh + ((size_t)(n * NPLANE + p)) * 128 + c0 + ch * 8, sz);
            }
        }
        asm volatile("cp.async.commit_group;" ::: "memory");
    };

    auto load_B = [&](int u) {
        const int q = u % 9, chunk = u / 9, c0 = chunk * 64;
        const uint32_t bbase = sd + B_BASE + (u & 1) * B_STAGE;
        #pragma unroll
        for (int it = 0; it < 2; ++it) {
            int idx = it * 512 + tid;
            int row = idx >> 3, ch = idx & 7;
            CP_ASYNC16(bbase + row * ROWB + ch * 16,
                       g_wh + (size_t)((q * 128 + row) * 128) + c0 + ch * 8, 16);
        }
        asm volatile("cp.async.commit_group;" ::: "memory");
    };

    float acc[2][4][4];
    #pragma unroll
    for (int i = 0; i < 2; ++i)
        #pragma unroll
        for (int j = 0; j < 4; ++j)
            #pragma unroll
            for (int r = 0; r < 4; ++r) acc[i][j][r] = 0.0f;

    const uint32_t a_lrow = (uint32_t)(wm * 32 + (lane & 15)) * ROWB + ((lane >> 4) << 4);
    const uint32_t b_lrow = (uint32_t)(wn * 32 + ((lane >> 4) << 3) + (lane & 7)) * ROWB
                            + ((lane & 8) ? 16u : 0u);

    load_A(0);
    load_A(1);
    load_B(0);
    load_B(1);

    for (int u = 0; u < NUNITS; ++u) {
        asm volatile("cp.async.wait_group 0;" ::: "memory");
        __syncthreads();
        if (u + 1 < NUNITS) load_B(u + 1);

        const int q = u % 9, chunk = u / 9;
        const int shift = (q / 3) * 34 + (q % 3);
        const uint32_t abase = sd + chunk * A_STAGE + (uint32_t)shift * ROWB + a_lrow;
        const uint32_t bbase = sd + B_BASE + (u & 1) * B_STAGE + b_lrow;

        #pragma unroll
        for (int ks = 0; ks < 4; ++ks) {
            uint32_t Ah[8], Bh[8];
            const uint32_t ao = abase + ks * 32;
            ldm_x4(&Ah[0], ao);
            ldm_x4(&Ah[4], ao + 16 * ROWB);
            const uint32_t bo = bbase + ks * 32;
            ldm_x4(&Bh[0], bo);
            ldm_x4(&Bh[4], bo + 16 * ROWB);

            #pragma unroll
            for (int i = 0; i < 2; ++i)
                #pragma unroll
                for (int j = 0; j < 4; ++j)
                    mma_f16(acc[i][j], &Ah[4 * i], &Bh[(j >> 1) * 4 + (j & 1) * 2]);
        }
        __syncthreads();
    }

    // ---------------- epilogue: 2 f-chunks of 16 via smem ----------------
    float* eps = (float*)dynsmem + wid * (32 * EPSTRIDE);
    const int g = lane >> 2, tg = lane & 3;
    const int mwbase = m0 + wm * 32;
    float* outn = out + (size_t)n * 128 * 1024;

    #pragma unroll
    for (int cj = 0; cj < 2; ++cj) {
        __syncwarp();
        #pragma unroll
        for (int i = 0; i < 2; ++i)
            #pragma unroll
            for (int jj = 0; jj < 2; ++jj) {
                int j = cj * 2 + jj;
                float* p0 = &eps[(i * 16 + g) * EPSTRIDE + jj * 8 + 2 * tg];
                float* p1 = &eps[(i * 16 + g + 8) * EPSTRIDE + jj * 8 + 2 * tg];
                *(float2*)p0 = make_float2(acc[i][j][0], acc[i][j][1]);
                *(float2*)p1 = make_float2(acc[i][j][2], acc[i][j][3]);
            }
        __syncwarp();

        #pragma unroll 1
        for (int f = 0; f < 16; ++f) {
            const int fg = wn * 32 + cj * 16 + f;
            const float bv = bias_s[fg];
            int m = mwbase + lane;
            int hh = m / 34, ww = m % 34;
            if (hh < 32 && ww < 32)
                outn[(size_t)fg * 1024 + hh * 32 + ww] = eps[lane * EPSTRIDE + f] + bv;
        }
    }
}

// ---------------- launch ----------------

extern "C" void kernel_launch(void* const* d_in, const int* in_sizes, int n_in,
                              void* d_out, int out_size) {
    const float* x = (const float*)d_in[0];
    const float* w = (const float*)d_in[1];
    const float* b = (const float*)d_in[2];
    float* out = (float*)d_out;

    cudaFuncSetAttribute(conv_hmma, cudaFuncAttributeMaxDynamicSharedMemorySize, SMEM_DYN);

    dim3 gp(38, 32);
    prep_all<<<gp, 256>>>(x, w);
    conv_hmma<<<288, 512, SMEM_DYN>>>(b, out);
}